// round 15
// baseline (speedup 1.0000x reference)
#include <cuda_runtime.h>
#include <cuda_bf16.h>
#include <math.h>
#include <stdint.h>

#define SEQ   2048
#define HID   1024
#define KDIM  1024
#define NH    16
#define NKV   4
#define DH    64
#define WIN   64

// ---------------------------------------------------------------------------
// Scratch (device globals — no allocation allowed)
// ---------------------------------------------------------------------------
__device__ float g_q[SEQ * HID];
__device__ float g_k[SEQ * NKV * DH];
__device__ float g_v[SEQ * NKV * DH];
__device__ float2 g_sc[SEQ * 32];

__device__ __nv_bfloat16 g_ah[SEQ * KDIM],  g_al[SEQ * KDIM];    // hidden split
__device__ __nv_bfloat16 g_b1h[1536 * KDIM], g_b1l[1536 * KDIM]; // qkv W^T split
__device__ __nv_bfloat16 g_b2h[1024 * KDIM], g_b2l[1024 * KDIM]; // o W^T split
__device__ __nv_bfloat16 g_ch[SEQ * KDIM],  g_cl[SEQ * KDIM];    // attn-out split

// ---------------------------------------------------------------------------
// Baseline-PTX async-copy / ldmatrix / mma helpers (sm_80+, legal in compute_103)
// ---------------------------------------------------------------------------
__device__ __forceinline__ uint32_t smem_u32(const void* p) {
    uint32_t a;
    asm("{ .reg .u64 t; cvta.to.shared.u64 t, %1; cvt.u32.u64 %0, t; }"
        : "=r"(a) : "l"(p));
    return a;
}
__device__ __forceinline__ void cp_async16(uint32_t d, const void* s) {
    asm volatile("cp.async.cg.shared.global [%0], [%1], 16;" :: "r"(d), "l"(s));
}
__device__ __forceinline__ void cp_commit() {
    asm volatile("cp.async.commit_group;" ::: "memory");
}
template <int N> __device__ __forceinline__ void cp_wait() {
    asm volatile("cp.async.wait_group %0;" :: "n"(N) : "memory");
}
__device__ __forceinline__ void ldm_x4(uint32_t* r, uint32_t addr) {
    asm volatile("ldmatrix.sync.aligned.m8n8.x4.shared.b16 {%0,%1,%2,%3}, [%4];"
                 : "=r"(r[0]), "=r"(r[1]), "=r"(r[2]), "=r"(r[3]) : "r"(addr));
}
__device__ __forceinline__ void mma_bf16(float* c, const uint32_t* a,
                                         const uint32_t* b) {
    asm volatile("mma.sync.aligned.m16n8k16.row.col.f32.bf16.bf16.f32 "
                 "{%0,%1,%2,%3}, {%4,%5,%6,%7}, {%8,%9}, {%0,%1,%2,%3};"
                 : "+f"(c[0]), "+f"(c[1]), "+f"(c[2]), "+f"(c[3])
                 : "r"(a[0]), "r"(a[1]), "r"(a[2]), "r"(a[3]),
                   "r"(b[0]), "r"(b[1]));
}

// ---------------------------------------------------------------------------
// Conversion kernels (fp32 -> bf16 hi/lo split)
// ---------------------------------------------------------------------------
__global__ void convert_split(const float* __restrict__ x,
                              __nv_bfloat16* __restrict__ hi,
                              __nv_bfloat16* __restrict__ lo, int n4) {
    int i = blockIdx.x * blockDim.x + threadIdx.x;
    if (i >= n4) return;
    float4 v = ((const float4*)x)[i];
    __nv_bfloat16 h0 = __float2bfloat16_rn(v.x);
    __nv_bfloat16 h1 = __float2bfloat16_rn(v.y);
    __nv_bfloat16 h2 = __float2bfloat16_rn(v.z);
    __nv_bfloat16 h3 = __float2bfloat16_rn(v.w);
    __nv_bfloat16 l0 = __float2bfloat16_rn(v.x - __bfloat162float(h0));
    __nv_bfloat16 l1 = __float2bfloat16_rn(v.y - __bfloat162float(h1));
    __nv_bfloat16 l2 = __float2bfloat16_rn(v.z - __bfloat162float(h2));
    __nv_bfloat16 l3 = __float2bfloat16_rn(v.w - __bfloat162float(h3));
    ((__nv_bfloat162*)hi)[i * 2]     = __nv_bfloat162(h0, h1);
    ((__nv_bfloat162*)hi)[i * 2 + 1] = __nv_bfloat162(h2, h3);
    ((__nv_bfloat162*)lo)[i * 2]     = __nv_bfloat162(l0, l1);
    ((__nv_bfloat162*)lo)[i * 2 + 1] = __nv_bfloat162(l2, l3);
}

// Merged transpose+split of all 4 weights: w[K][Nsrc] -> dst[(roff+n)][k]
__global__ void convert_wT_all(const float* __restrict__ qw,
                               const float* __restrict__ kw,
                               const float* __restrict__ vw,
                               const float* __restrict__ ow) {
    __shared__ float t[32][33];
    int b = blockIdx.x;
    const float* w;
    __nv_bfloat16 *th, *tl;
    int Nsrc, roff, local;
    if (b < 1024)      { w = qw; th = g_b1h; tl = g_b1l; Nsrc = 1024; roff = 0;    local = b; }
    else if (b < 1280) { w = kw; th = g_b1h; tl = g_b1l; Nsrc = 256;  roff = 1024; local = b - 1024; }
    else if (b < 1536) { w = vw; th = g_b1h; tl = g_b1l; Nsrc = 256;  roff = 1280; local = b - 1280; }
    else               { w = ow; th = g_b2h; tl = g_b2l; Nsrc = 1024; roff = 0;    local = b - 1536; }
    int ntn = Nsrc / 32;
    int nb = (local % ntn) * 32;
    int kb = (local / ntn) * 32;
    int tx = threadIdx.x, ty = threadIdx.y;   // (32, 8)
    #pragma unroll
    for (int j = 0; j < 32; j += 8)
        t[ty + j][tx] = w[(size_t)(kb + ty + j) * Nsrc + nb + tx];
    __syncthreads();
    #pragma unroll
    for (int j = 0; j < 32; j += 8) {
        float x = t[tx][ty + j];
        __nv_bfloat16 h = __float2bfloat16_rn(x);
        __nv_bfloat16 l = __float2bfloat16_rn(x - __bfloat162float(h));
        size_t o = (size_t)(roff + nb + ty + j) * KDIM + kb + tx;
        th[o] = h;
        tl[o] = l;
    }
}

// ---------------------------------------------------------------------------
// HMMA GEMM: C = A @ B^T, bf16-split 3-term, fp32 accum.
// CTA tile 128x64, K chunks of 32, cp.async double buffer, 8 warps (4x2),
// each warp 32x32 via 2x4 m16n8k16 tiles. 3 CTAs/SM.  (R7 config — final)
// mode 0: qkv demux (blockIdx.y -> g_q/g_k/g_v). mode 1: write Cout.
// ---------------------------------------------------------------------------
#define BK      32
#define ROWB    80
#define AMATB   (128 * ROWB)
#define BMATB   (64 * ROWB)
#define STAGEB  (2 * AMATB + 2 * BMATB)   // 30720
#define GSMEM   (2 * STAGEB)              // 61440

__global__ __launch_bounds__(256, 3) void gemm_mma(
    const __nv_bfloat16* __restrict__ Ah, const __nv_bfloat16* __restrict__ Al,
    const __nv_bfloat16* __restrict__ Bh, const __nv_bfloat16* __restrict__ Bl,
    float* __restrict__ Cout, int mode) {
    extern __shared__ char smem[];
    const uint32_t sb = smem_u32(smem);
    const int tid = threadIdx.x;
    const int wid = tid >> 5, lane = tid & 31;
    const int wm = wid >> 1, wn = wid & 1;
    const int m0 = blockIdx.x * 128;
    const int nt = blockIdx.y;
    const int n0 = nt * 64;

    const __nv_bfloat16* gA[2] = { Ah + (size_t)m0 * KDIM, Al + (size_t)m0 * KDIM };
    const __nv_bfloat16* gB[2] = { Bh + (size_t)n0 * KDIM, Bl + (size_t)n0 * KDIM };

    const int arow  = tid >> 1;
    const int ahalf = tid & 1;
    const int brow = tid >> 2;
    const int bseg = tid & 3;

    const int g2    = lane >> 3;
    const int rsub  = ((g2 & 1) << 3) + (lane & 7);
    const int ksubA = (g2 >> 1) * 8;
    const int rsubB = ((g2 >> 1) << 3) + (lane & 7);
    const int ksubB = (g2 & 1) * 8;

    float acc[2][4][4] = {};

    const int NC = KDIM / BK;
    auto load_stage = [&](int c, int buf) {
        uint32_t base = sb + buf * STAGEB;
        const int kc = c * BK;
        #pragma unroll
        for (int m = 0; m < 2; m++) {
            const __nv_bfloat16* src = gA[m] + (size_t)arow * KDIM + kc + ahalf * 16;
            uint32_t dst = base + m * AMATB + arow * ROWB + ahalf * 32;
            cp_async16(dst, src);
            cp_async16(dst + 16, src + 8);
        }
        #pragma unroll
        for (int m = 0; m < 2; m++) {
            const __nv_bfloat16* src = gB[m] + (size_t)brow * KDIM + kc + bseg * 8;
            uint32_t dst = base + 2 * AMATB + m * BMATB + brow * ROWB + bseg * 16;
            cp_async16(dst, src);
        }
        cp_commit();
    };

    load_stage(0, 0);

    for (int c = 0; c < NC; c++) {
        const int buf = c & 1;
        if (c + 1 < NC) {
            load_stage(c + 1, buf ^ 1);
            cp_wait<1>();
        } else {
            cp_wait<0>();
        }
        __syncthreads();

        const uint32_t stage = sb + buf * STAGEB;
        const uint32_t aBase = stage;
        const uint32_t bBase = stage + 2 * AMATB;
        #pragma unroll
        for (int ks = 0; ks < 2; ks++) {
            uint32_t afr[2][4], bhf[2][4], blf[2][4];
            #pragma unroll
            for (int mt = 0; mt < 2; mt++)
                ldm_x4(afr[mt], aBase +
                       (wm * 32 + mt * 16 + rsub) * ROWB + (ks * 16 + ksubA) * 2);
            #pragma unroll
            for (int p = 0; p < 2; p++)
                ldm_x4(bhf[p], bBase +
                       (wn * 32 + p * 16 + rsubB) * ROWB + (ks * 16 + ksubB) * 2);
            #pragma unroll
            for (int mt = 0; mt < 2; mt++)
                #pragma unroll
                for (int n4 = 0; n4 < 4; n4++)
                    mma_bf16(acc[mt][n4], afr[mt], &bhf[n4 >> 1][(n4 & 1) * 2]);
            #pragma unroll
            for (int p = 0; p < 2; p++)
                ldm_x4(blf[p], bBase + BMATB +
                       (wn * 32 + p * 16 + rsubB) * ROWB + (ks * 16 + ksubB) * 2);
            #pragma unroll
            for (int mt = 0; mt < 2; mt++)
                #pragma unroll
                for (int n4 = 0; n4 < 4; n4++)
                    mma_bf16(acc[mt][n4], afr[mt], &blf[n4 >> 1][(n4 & 1) * 2]);
            #pragma unroll
            for (int mt = 0; mt < 2; mt++)
                ldm_x4(afr[mt], aBase + AMATB +
                       (wm * 32 + mt * 16 + rsub) * ROWB + (ks * 16 + ksubA) * 2);
            #pragma unroll
            for (int mt = 0; mt < 2; mt++)
                #pragma unroll
                for (int n4 = 0; n4 < 4; n4++)
                    mma_bf16(acc[mt][n4], afr[mt], &bhf[n4 >> 1][(n4 & 1) * 2]);
        }
        __syncthreads();
    }

    float* C;
    int Nc, nc0;
    if (mode == 0) {
        if (nt < 16)      { C = g_q; Nc = HID;      nc0 = n0; }
        else if (nt < 20) { C = g_k; Nc = NKV * DH; nc0 = (nt - 16) * 64; }
        else              { C = g_v; Nc = NKV * DH; nc0 = (nt - 20) * 64; }
    } else { C = Cout; Nc = HID; nc0 = n0; }
    const int rbase = m0 + wm * 32 + (lane >> 2);
    const int cbase = nc0 + wn * 32 + (lane & 3) * 2;
    #pragma unroll
    for (int mt = 0; mt < 2; mt++)
        #pragma unroll
        for (int n4 = 0; n4 < 4; n4++) {
            int r = rbase + mt * 16;
            int cc = cbase + n4 * 8;
            *(float2*)(C + (size_t)r * Nc + cc) =
                make_float2(acc[mt][n4][0], acc[mt][n4][1]);
            *(float2*)(C + (size_t)(r + 8) * Nc + cc) =
                make_float2(acc[mt][n4][2], acc[mt][n4][3]);
        }
}

// ---------------------------------------------------------------------------
// Sincos table — FP64 pow only for the 32-entry inv_freq table (per block),
// FP64 multiply for the angle (matches reference float64 semantics), then
// accurate float sincosf on the float32 angle (~1e-7 vs double-sin-of-float).
// ---------------------------------------------------------------------------
__global__ void sincos_table_kernel(const int* __restrict__ pos_ids) {
    __shared__ double invf_s[32];
    int tid = threadIdx.x;
    if (tid < 32)
        invf_s[tid] = pow(10000.0, -(double)tid / 32.0);
    __syncthreads();
    int idx = blockIdx.x * blockDim.x + tid;
    if (idx >= SEQ * 32) return;
    int i = idx & 31;
    int s = idx >> 5;
    int pos = pos_ids[s];
    float ang = (float)((double)pos * invf_s[i]);   // reference rounds to f32
    float sf, cf;
    sincosf(ang, &sf, &cf);
    g_sc[idx] = make_float2(sf, cf);
}

// ---------------------------------------------------------------------------
// Sliding-window attention with fused RoPE (staging) and fused bf16-split
// output (epilogue). Block = (32-query tile, kv head).  (R7 version — final)
// ---------------------------------------------------------------------------
#define ATTN_SMEM ((64 * 97 + 95 * 64 + 128 * 64 + 8 * 4 * 64) * 4)

__global__ __launch_bounds__(256) void attn_kernel(const int* __restrict__ mask) {
    extern __shared__ float smarr[];
    float* kT = smarr;              // [64 d][97]
    float* vS = kT + 64 * 97;       // [95][64]
    float* qs = vS + 95 * 64;       // [128][64]  row r = sl*4 + h
    float* ps = qs + 128 * 64;      // [8 warps][4 h][64]

    const int g  = blockIdx.y;
    const int s0 = blockIdx.x * 32;
    const int tid = threadIdx.x;

    for (int idx = tid; idx < 95 * 32; idx += 256) {
        int j = idx >> 5;
        int d = idx & 31;
        int jg = s0 - 63 + j;
        float r0 = 0.f, r1 = 0.f, v0 = 0.f, v1 = 0.f;
        if (jg >= 0) {
            size_t off = (size_t)jg * (NKV * DH) + g * DH + d;
            float x0 = g_k[off];
            float x1 = g_k[off + 32];
            float2 sc = g_sc[jg * 32 + d];
            r0 = x0 * sc.y - x1 * sc.x;
            r1 = x1 * sc.y + x0 * sc.x;
            v0 = g_v[off];
            v1 = g_v[off + 32];
        }
        kT[d * 97 + j]        = r0;
        kT[(d + 32) * 97 + j] = r1;
        vS[j * 64 + d]        = v0;
        vS[j * 64 + d + 32]   = v1;
    }
    for (int idx = tid; idx < 128 * 32; idx += 256) {
        int r = idx >> 5;
        int d = idx & 31;
        int sl = r >> 2;
        int hl = r & 3;
        int s  = s0 + sl;
        size_t off = (size_t)s * HID + (4 * g + hl) * DH + d;
        float x0 = g_q[off];
        float x1 = g_q[off + 32];
        float2 sc = g_sc[s * 32 + d];
        qs[r * 64 + d]      = x0 * sc.y - x1 * sc.x;
        qs[r * 64 + d + 32] = x1 * sc.y + x0 * sc.x;
    }
    __syncthreads();

    const int warp = tid >> 5;
    const int lane = tid & 31;

    for (int sl_i = 0; sl_i < 4; sl_i++) {
        const int sl = warp * 4 + sl_i;
        const int s  = s0 + sl;
        const int jb = sl;

        float sc0[4] = {}, sc1[4] = {};
        #pragma unroll
        for (int d = 0; d < 64; d++) {
            const float* kr = kT + d * 97 + jb;
            float k0 = kr[lane];
            float k1 = kr[lane + 32];
            #pragma unroll
            for (int h = 0; h < 4; h++) {
                float qd = qs[(sl * 4 + h) * 64 + d];
                sc0[h] += qd * k0;
                sc1[h] += qd * k1;
            }
        }
        const int* mrow = mask + (size_t)s * WIN;
        bool mk0 = mrow[lane] <= 0;
        bool mk1 = mrow[lane + 32] <= 0;

        #pragma unroll
        for (int h = 0; h < 4; h++) {
            float a0 = mk0 ? -1e30f : sc0[h] * 0.125f;
            float a1 = mk1 ? -1e30f : sc1[h] * 0.125f;
            float mx = fmaxf(a0, a1);
            #pragma unroll
            for (int o = 16; o; o >>= 1)
                mx = fmaxf(mx, __shfl_xor_sync(0xffffffffu, mx, o));
            float e0 = __expf(a0 - mx);
            float e1 = __expf(a1 - mx);
            float sum = e0 + e1;
            #pragma unroll
            for (int o = 16; o; o >>= 1)
                sum += __shfl_xor_sync(0xffffffffu, sum, o);
            float inv = 1.f / sum;
            float* pr = ps + (warp * 4 + h) * 64;
            pr[lane]      = e0 * inv;
            pr[lane + 32] = e1 * inv;
        }
        __syncwarp();

        float o0[4] = {}, o1[4] = {};
        const int d0 = lane * 2;
        #pragma unroll
        for (int w = 0; w < 64; w++) {
            float2 vv = *(const float2*)&vS[(jb + w) * 64 + d0];
            #pragma unroll
            for (int h = 0; h < 4; h++) {
                float p = ps[(warp * 4 + h) * 64 + w];
                o0[h] += p * vv.x;
                o1[h] += p * vv.y;
            }
        }
        __syncwarp();

        #pragma unroll
        for (int h = 0; h < 4; h++) {
            size_t off = (size_t)s * HID + (4 * g + h) * DH + d0;
            __nv_bfloat16 h0 = __float2bfloat16_rn(o0[h]);
            __nv_bfloat16 h1 = __float2bfloat16_rn(o1[h]);
            __nv_bfloat16 l0 = __float2bfloat16_rn(o0[h] - __bfloat162float(h0));
            __nv_bfloat16 l1 = __float2bfloat16_rn(o1[h] - __bfloat162float(h1));
            *(__nv_bfloat162*)(g_ch + off) = __nv_bfloat162(h0, h1);
            *(__nv_bfloat162*)(g_cl + off) = __nv_bfloat162(l0, l1);
        }
    }
}

// ---------------------------------------------------------------------------
extern "C" void kernel_launch(void* const* d_in, const int* in_sizes, int n_in,
                              void* d_out, int out_size) {
    const float* hidden = (const float*)d_in[0];
    const int*   mask   = (const int*)d_in[1];
    const int*   pos    = (const int*)d_in[2];
    const float* qw     = (const float*)d_in[3];
    const float* kw     = (const float*)d_in[4];
    const float* vw     = (const float*)d_in[5];
    const float* ow     = (const float*)d_in[6];
    float* out = (float*)d_out;

    __nv_bfloat16 *ah, *al, *b1h, *b1l, *b2h, *b2l, *chh, *cll;
    cudaGetSymbolAddress((void**)&ah,  g_ah);
    cudaGetSymbolAddress((void**)&al,  g_al);
    cudaGetSymbolAddress((void**)&b1h, g_b1h);
    cudaGetSymbolAddress((void**)&b1l, g_b1l);
    cudaGetSymbolAddress((void**)&b2h, g_b2h);
    cudaGetSymbolAddress((void**)&b2l, g_b2l);
    cudaGetSymbolAddress((void**)&chh, g_ch);
    cudaGetSymbolAddress((void**)&cll, g_cl);

    cudaFuncSetAttribute(gemm_mma, cudaFuncAttributeMaxDynamicSharedMemorySize,
                         GSMEM);
    cudaFuncSetAttribute(attn_kernel, cudaFuncAttributeMaxDynamicSharedMemorySize,
                         ATTN_SMEM);

    sincos_table_kernel<<<(SEQ * 32 + 255) / 256, 256>>>(pos);

    convert_split<<<(SEQ * KDIM / 4 + 255) / 256, 256>>>(hidden, ah, al,
                                                         SEQ * KDIM / 4);
    convert_wT_all<<<2560, dim3(32, 8)>>>(qw, kw, vw, ow);

    gemm_mma<<<dim3(SEQ / 128, 24), 256, GSMEM>>>(ah, al, b1h, b1l, nullptr, 0);

    attn_kernel<<<dim3(SEQ / 32, NKV), 256, ATTN_SMEM>>>(mask);

    gemm_mma<<<dim3(SEQ / 128, 16), 256, GSMEM>>>(chh, cll, b2h, b2l, out, 1);
}

// round 16
// speedup vs baseline: 1.4147x; 1.4147x over previous
#include <cuda_runtime.h>
#include <cuda_bf16.h>
#include <math.h>
#include <stdint.h>

#define SEQ   2048
#define HID   1024
#define KDIM  1024
#define NH    16
#define NKV   4
#define DH    64
#define WIN   64

// ---------------------------------------------------------------------------
// Scratch (device globals — no allocation allowed)
// ---------------------------------------------------------------------------
__device__ float g_q[SEQ * HID];
__device__ float g_k[SEQ * NKV * DH];
__device__ float g_v[SEQ * NKV * DH];
__device__ float2 g_sc[SEQ * 32];

__device__ __nv_bfloat16 g_ah[SEQ * KDIM],  g_al[SEQ * KDIM];    // hidden split
__device__ __nv_bfloat16 g_b1h[1536 * KDIM], g_b1l[1536 * KDIM]; // qkv W^T split
__device__ __nv_bfloat16 g_b2h[1024 * KDIM], g_b2l[1024 * KDIM]; // o W^T split
__device__ __nv_bfloat16 g_ch[SEQ * KDIM],  g_cl[SEQ * KDIM];    // attn-out split

// ---------------------------------------------------------------------------
// Baseline-PTX async-copy / ldmatrix / mma helpers (sm_80+, legal in compute_103)
// ---------------------------------------------------------------------------
__device__ __forceinline__ uint32_t smem_u32(const void* p) {
    uint32_t a;
    asm("{ .reg .u64 t; cvta.to.shared.u64 t, %1; cvt.u32.u64 %0, t; }"
        : "=r"(a) : "l"(p));
    return a;
}
__device__ __forceinline__ void cp_async16(uint32_t d, const void* s) {
    asm volatile("cp.async.cg.shared.global [%0], [%1], 16;" :: "r"(d), "l"(s));
}
__device__ __forceinline__ void cp_commit() {
    asm volatile("cp.async.commit_group;" ::: "memory");
}
template <int N> __device__ __forceinline__ void cp_wait() {
    asm volatile("cp.async.wait_group %0;" :: "n"(N) : "memory");
}
__device__ __forceinline__ void ldm_x4(uint32_t* r, uint32_t addr) {
    asm volatile("ldmatrix.sync.aligned.m8n8.x4.shared.b16 {%0,%1,%2,%3}, [%4];"
                 : "=r"(r[0]), "=r"(r[1]), "=r"(r[2]), "=r"(r[3]) : "r"(addr));
}
__device__ __forceinline__ void mma_bf16(float* c, const uint32_t* a,
                                         const uint32_t* b) {
    asm volatile("mma.sync.aligned.m16n8k16.row.col.f32.bf16.bf16.f32 "
                 "{%0,%1,%2,%3}, {%4,%5,%6,%7}, {%8,%9}, {%0,%1,%2,%3};"
                 : "+f"(c[0]), "+f"(c[1]), "+f"(c[2]), "+f"(c[3])
                 : "r"(a[0]), "r"(a[1]), "r"(a[2]), "r"(a[3]),
                   "r"(b[0]), "r"(b[1]));
}

// ---------------------------------------------------------------------------
// Conversion kernels (fp32 -> bf16 hi/lo split)
// ---------------------------------------------------------------------------
__global__ void convert_split(const float* __restrict__ x,
                              __nv_bfloat16* __restrict__ hi,
                              __nv_bfloat16* __restrict__ lo, int n4) {
    int i = blockIdx.x * blockDim.x + threadIdx.x;
    if (i >= n4) return;
    float4 v = ((const float4*)x)[i];
    __nv_bfloat16 h0 = __float2bfloat16_rn(v.x);
    __nv_bfloat16 h1 = __float2bfloat16_rn(v.y);
    __nv_bfloat16 h2 = __float2bfloat16_rn(v.z);
    __nv_bfloat16 h3 = __float2bfloat16_rn(v.w);
    __nv_bfloat16 l0 = __float2bfloat16_rn(v.x - __bfloat162float(h0));
    __nv_bfloat16 l1 = __float2bfloat16_rn(v.y - __bfloat162float(h1));
    __nv_bfloat16 l2 = __float2bfloat16_rn(v.z - __bfloat162float(h2));
    __nv_bfloat16 l3 = __float2bfloat16_rn(v.w - __bfloat162float(h3));
    ((__nv_bfloat162*)hi)[i * 2]     = __nv_bfloat162(h0, h1);
    ((__nv_bfloat162*)hi)[i * 2 + 1] = __nv_bfloat162(h2, h3);
    ((__nv_bfloat162*)lo)[i * 2]     = __nv_bfloat162(l0, l1);
    ((__nv_bfloat162*)lo)[i * 2 + 1] = __nv_bfloat162(l2, l3);
}

// Merged transpose+split of all 4 weights: w[K][Nsrc] -> dst[(roff+n)][k]
__global__ void convert_wT_all(const float* __restrict__ qw,
                               const float* __restrict__ kw,
                               const float* __restrict__ vw,
                               const float* __restrict__ ow) {
    __shared__ float t[32][33];
    int b = blockIdx.x;
    const float* w;
    __nv_bfloat16 *th, *tl;
    int Nsrc, roff, local;
    if (b < 1024)      { w = qw; th = g_b1h; tl = g_b1l; Nsrc = 1024; roff = 0;    local = b; }
    else if (b < 1280) { w = kw; th = g_b1h; tl = g_b1l; Nsrc = 256;  roff = 1024; local = b - 1024; }
    else if (b < 1536) { w = vw; th = g_b1h; tl = g_b1l; Nsrc = 256;  roff = 1280; local = b - 1280; }
    else               { w = ow; th = g_b2h; tl = g_b2l; Nsrc = 1024; roff = 0;    local = b - 1536; }
    int ntn = Nsrc / 32;
    int nb = (local % ntn) * 32;
    int kb = (local / ntn) * 32;
    int tx = threadIdx.x, ty = threadIdx.y;   // (32, 8)
    #pragma unroll
    for (int j = 0; j < 32; j += 8)
        t[ty + j][tx] = w[(size_t)(kb + ty + j) * Nsrc + nb + tx];
    __syncthreads();
    #pragma unroll
    for (int j = 0; j < 32; j += 8) {
        float x = t[tx][ty + j];
        __nv_bfloat16 h = __float2bfloat16_rn(x);
        __nv_bfloat16 l = __float2bfloat16_rn(x - __bfloat162float(h));
        size_t o = (size_t)(roff + nb + ty + j) * KDIM + kb + tx;
        th[o] = h;
        tl[o] = l;
    }
}

// ---------------------------------------------------------------------------
// HMMA GEMM: C = A @ B^T, bf16-split 3-term, fp32 accum.
// CTA tile 128x64, K chunks of 32, cp.async double buffer, 8 warps (4x2),
// each warp 32x32 via 2x4 m16n8k16 tiles. 3 CTAs/SM.  (best-known config)
// mode 0: qkv demux (blockIdx.y -> g_q/g_k/g_v). mode 1: write Cout.
// ---------------------------------------------------------------------------
#define BK      32
#define ROWB    80
#define AMATB   (128 * ROWB)
#define BMATB   (64 * ROWB)
#define STAGEB  (2 * AMATB + 2 * BMATB)   // 30720
#define GSMEM   (2 * STAGEB)              // 61440

__global__ __launch_bounds__(256, 3) void gemm_mma(
    const __nv_bfloat16* __restrict__ Ah, const __nv_bfloat16* __restrict__ Al,
    const __nv_bfloat16* __restrict__ Bh, const __nv_bfloat16* __restrict__ Bl,
    float* __restrict__ Cout, int mode) {
    extern __shared__ char smem[];
    const uint32_t sb = smem_u32(smem);
    const int tid = threadIdx.x;
    const int wid = tid >> 5, lane = tid & 31;
    const int wm = wid >> 1, wn = wid & 1;
    const int m0 = blockIdx.x * 128;
    const int nt = blockIdx.y;
    const int n0 = nt * 64;

    const __nv_bfloat16* gA[2] = { Ah + (size_t)m0 * KDIM, Al + (size_t)m0 * KDIM };
    const __nv_bfloat16* gB[2] = { Bh + (size_t)n0 * KDIM, Bl + (size_t)n0 * KDIM };

    const int arow  = tid >> 1;
    const int ahalf = tid & 1;
    const int brow = tid >> 2;
    const int bseg = tid & 3;

    const int g2    = lane >> 3;
    const int rsub  = ((g2 & 1) << 3) + (lane & 7);
    const int ksubA = (g2 >> 1) * 8;
    const int rsubB = ((g2 >> 1) << 3) + (lane & 7);
    const int ksubB = (g2 & 1) * 8;

    float acc[2][4][4] = {};

    const int NC = KDIM / BK;
    auto load_stage = [&](int c, int buf) {
        uint32_t base = sb + buf * STAGEB;
        const int kc = c * BK;
        #pragma unroll
        for (int m = 0; m < 2; m++) {
            const __nv_bfloat16* src = gA[m] + (size_t)arow * KDIM + kc + ahalf * 16;
            uint32_t dst = base + m * AMATB + arow * ROWB + ahalf * 32;
            cp_async16(dst, src);
            cp_async16(dst + 16, src + 8);
        }
        #pragma unroll
        for (int m = 0; m < 2; m++) {
            const __nv_bfloat16* src = gB[m] + (size_t)brow * KDIM + kc + bseg * 8;
            uint32_t dst = base + 2 * AMATB + m * BMATB + brow * ROWB + bseg * 16;
            cp_async16(dst, src);
        }
        cp_commit();
    };

    load_stage(0, 0);

    for (int c = 0; c < NC; c++) {
        const int buf = c & 1;
        if (c + 1 < NC) {
            load_stage(c + 1, buf ^ 1);
            cp_wait<1>();
        } else {
            cp_wait<0>();
        }
        __syncthreads();

        const uint32_t stage = sb + buf * STAGEB;
        const uint32_t aBase = stage;
        const uint32_t bBase = stage + 2 * AMATB;
        #pragma unroll
        for (int ks = 0; ks < 2; ks++) {
            uint32_t afr[2][4], bhf[2][4], blf[2][4];
            #pragma unroll
            for (int mt = 0; mt < 2; mt++)
                ldm_x4(afr[mt], aBase +
                       (wm * 32 + mt * 16 + rsub) * ROWB + (ks * 16 + ksubA) * 2);
            #pragma unroll
            for (int p = 0; p < 2; p++)
                ldm_x4(bhf[p], bBase +
                       (wn * 32 + p * 16 + rsubB) * ROWB + (ks * 16 + ksubB) * 2);
            #pragma unroll
            for (int mt = 0; mt < 2; mt++)
                #pragma unroll
                for (int n4 = 0; n4 < 4; n4++)
                    mma_bf16(acc[mt][n4], afr[mt], &bhf[n4 >> 1][(n4 & 1) * 2]);
            #pragma unroll
            for (int p = 0; p < 2; p++)
                ldm_x4(blf[p], bBase + BMATB +
                       (wn * 32 + p * 16 + rsubB) * ROWB + (ks * 16 + ksubB) * 2);
            #pragma unroll
            for (int mt = 0; mt < 2; mt++)
                #pragma unroll
                for (int n4 = 0; n4 < 4; n4++)
                    mma_bf16(acc[mt][n4], afr[mt], &blf[n4 >> 1][(n4 & 1) * 2]);
            #pragma unroll
            for (int mt = 0; mt < 2; mt++)
                ldm_x4(afr[mt], aBase + AMATB +
                       (wm * 32 + mt * 16 + rsub) * ROWB + (ks * 16 + ksubA) * 2);
            #pragma unroll
            for (int mt = 0; mt < 2; mt++)
                #pragma unroll
                for (int n4 = 0; n4 < 4; n4++)
                    mma_bf16(acc[mt][n4], afr[mt], &bhf[n4 >> 1][(n4 & 1) * 2]);
        }
        __syncthreads();
    }

    float* C;
    int Nc, nc0;
    if (mode == 0) {
        if (nt < 16)      { C = g_q; Nc = HID;      nc0 = n0; }
        else if (nt < 20) { C = g_k; Nc = NKV * DH; nc0 = (nt - 16) * 64; }
        else              { C = g_v; Nc = NKV * DH; nc0 = (nt - 20) * 64; }
    } else { C = Cout; Nc = HID; nc0 = n0; }
    const int rbase = m0 + wm * 32 + (lane >> 2);
    const int cbase = nc0 + wn * 32 + (lane & 3) * 2;
    #pragma unroll
    for (int mt = 0; mt < 2; mt++)
        #pragma unroll
        for (int n4 = 0; n4 < 4; n4++) {
            int r = rbase + mt * 16;
            int cc = cbase + n4 * 8;
            *(float2*)(C + (size_t)r * Nc + cc) =
                make_float2(acc[mt][n4][0], acc[mt][n4][1]);
            *(float2*)(C + (size_t)(r + 8) * Nc + cc) =
                make_float2(acc[mt][n4][2], acc[mt][n4][3]);
        }
}

// ---------------------------------------------------------------------------
// Sincos table
// ---------------------------------------------------------------------------
__global__ void sincos_table_kernel(const int* __restrict__ pos_ids) {
    int idx = blockIdx.x * blockDim.x + threadIdx.x;
    if (idx >= SEQ * 32) return;
    int i = idx & 31;
    int s = idx >> 5;
    int pos = pos_ids[s];
    double invf = pow(10000.0, -(double)i / 32.0);
    float ang = (float)((double)pos * invf);
    double sd, cd;
    sincos((double)ang, &sd, &cd);
    g_sc[idx] = make_float2((float)sd, (float)cd);
}

// ---------------------------------------------------------------------------
// Sliding-window attention with fused RoPE (staging) and fused bf16-split
// output (epilogue). Block = (32-query tile, kv head).
// ---------------------------------------------------------------------------
#define ATTN_SMEM ((64 * 97 + 95 * 64 + 128 * 64 + 8 * 4 * 64) * 4)

__global__ __launch_bounds__(256) void attn_kernel(const int* __restrict__ mask) {
    extern __shared__ float smarr[];
    float* kT = smarr;              // [64 d][97]
    float* vS = kT + 64 * 97;       // [95][64]
    float* qs = vS + 95 * 64;       // [128][64]  row r = sl*4 + h
    float* ps = qs + 128 * 64;      // [8 warps][4 h][64]

    const int g  = blockIdx.y;
    const int s0 = blockIdx.x * 32;
    const int tid = threadIdx.x;

    for (int idx = tid; idx < 95 * 32; idx += 256) {
        int j = idx >> 5;
        int d = idx & 31;
        int jg = s0 - 63 + j;
        float r0 = 0.f, r1 = 0.f, v0 = 0.f, v1 = 0.f;
        if (jg >= 0) {
            size_t off = (size_t)jg * (NKV * DH) + g * DH + d;
            float x0 = g_k[off];
            float x1 = g_k[off + 32];
            float2 sc = g_sc[jg * 32 + d];
            r0 = x0 * sc.y - x1 * sc.x;
            r1 = x1 * sc.y + x0 * sc.x;
            v0 = g_v[off];
            v1 = g_v[off + 32];
        }
        kT[d * 97 + j]        = r0;
        kT[(d + 32) * 97 + j] = r1;
        vS[j * 64 + d]        = v0;
        vS[j * 64 + d + 32]   = v1;
    }
    for (int idx = tid; idx < 128 * 32; idx += 256) {
        int r = idx >> 5;
        int d = idx & 31;
        int sl = r >> 2;
        int hl = r & 3;
        int s  = s0 + sl;
        size_t off = (size_t)s * HID + (4 * g + hl) * DH + d;
        float x0 = g_q[off];
        float x1 = g_q[off + 32];
        float2 sc = g_sc[s * 32 + d];
        qs[r * 64 + d]      = x0 * sc.y - x1 * sc.x;
        qs[r * 64 + d + 32] = x1 * sc.y + x0 * sc.x;
    }
    __syncthreads();

    const int warp = tid >> 5;
    const int lane = tid & 31;

    for (int sl_i = 0; sl_i < 4; sl_i++) {
        const int sl = warp * 4 + sl_i;
        const int s  = s0 + sl;
        const int jb = sl;

        float sc0[4] = {}, sc1[4] = {};
        #pragma unroll
        for (int d = 0; d < 64; d++) {
            const float* kr = kT + d * 97 + jb;
            float k0 = kr[lane];
            float k1 = kr[lane + 32];
            #pragma unroll
            for (int h = 0; h < 4; h++) {
                float qd = qs[(sl * 4 + h) * 64 + d];
                sc0[h] += qd * k0;
                sc1[h] += qd * k1;
            }
        }
        const int* mrow = mask + (size_t)s * WIN;
        bool mk0 = mrow[lane] <= 0;
        bool mk1 = mrow[lane + 32] <= 0;

        #pragma unroll
        for (int h = 0; h < 4; h++) {
            float a0 = mk0 ? -1e30f : sc0[h] * 0.125f;
            float a1 = mk1 ? -1e30f : sc1[h] * 0.125f;
            float mx = fmaxf(a0, a1);
            #pragma unroll
            for (int o = 16; o; o >>= 1)
                mx = fmaxf(mx, __shfl_xor_sync(0xffffffffu, mx, o));
            float e0 = __expf(a0 - mx);
            float e1 = __expf(a1 - mx);
            float sum = e0 + e1;
            #pragma unroll
            for (int o = 16; o; o >>= 1)
                sum += __shfl_xor_sync(0xffffffffu, sum, o);
            float inv = 1.f / sum;
            float* pr = ps + (warp * 4 + h) * 64;
            pr[lane]      = e0 * inv;
            pr[lane + 32] = e1 * inv;
        }
        __syncwarp();

        float o0[4] = {}, o1[4] = {};
        const int d0 = lane * 2;
        #pragma unroll
        for (int w = 0; w < 64; w++) {
            float2 vv = *(const float2*)&vS[(jb + w) * 64 + d0];
            #pragma unroll
            for (int h = 0; h < 4; h++) {
                float p = ps[(warp * 4 + h) * 64 + w];
                o0[h] += p * vv.x;
                o1[h] += p * vv.y;
            }
        }
        __syncwarp();

        #pragma unroll
        for (int h = 0; h < 4; h++) {
            size_t off = (size_t)s * HID + (4 * g + h) * DH + d0;
            __nv_bfloat16 h0 = __float2bfloat16_rn(o0[h]);
            __nv_bfloat16 h1 = __float2bfloat16_rn(o1[h]);
            __nv_bfloat16 l0 = __float2bfloat16_rn(o0[h] - __bfloat162float(h0));
            __nv_bfloat16 l1 = __float2bfloat16_rn(o1[h] - __bfloat162float(h1));
            *(__nv_bfloat162*)(g_ch + off) = __nv_bfloat162(h0, h1);
            *(__nv_bfloat162*)(g_cl + off) = __nv_bfloat162(l0, l1);
        }
    }
}

// ---------------------------------------------------------------------------
extern "C" void kernel_launch(void* const* d_in, const int* in_sizes, int n_in,
                              void* d_out, int out_size) {
    const float* hidden = (const float*)d_in[0];
    const int*   mask   = (const int*)d_in[1];
    const int*   pos    = (const int*)d_in[2];
    const float* qw     = (const float*)d_in[3];
    const float* kw     = (const float*)d_in[4];
    const float* vw     = (const float*)d_in[5];
    const float* ow     = (const float*)d_in[6];
    float* out = (float*)d_out;

    __nv_bfloat16 *ah, *al, *b1h, *b1l, *b2h, *b2l, *chh, *cll;
    cudaGetSymbolAddress((void**)&ah,  g_ah);
    cudaGetSymbolAddress((void**)&al,  g_al);
    cudaGetSymbolAddress((void**)&b1h, g_b1h);
    cudaGetSymbolAddress((void**)&b1l, g_b1l);
    cudaGetSymbolAddress((void**)&b2h, g_b2h);
    cudaGetSymbolAddress((void**)&b2l, g_b2l);
    cudaGetSymbolAddress((void**)&chh, g_ch);
    cudaGetSymbolAddress((void**)&cll, g_cl);

    cudaFuncSetAttribute(gemm_mma, cudaFuncAttributeMaxDynamicSharedMemorySize,
                         GSMEM);
    cudaFuncSetAttribute(attn_kernel, cudaFuncAttributeMaxDynamicSharedMemorySize,
                         ATTN_SMEM);

    sincos_table_kernel<<<(SEQ * 32 + 255) / 256, 256>>>(pos);

    convert_split<<<(SEQ * KDIM / 4 + 255) / 256, 256>>>(hidden, ah, al,
                                                         SEQ * KDIM / 4);
    convert_wT_all<<<2560, dim3(32, 8)>>>(qw, kw, vw, ow);

    gemm_mma<<<dim3(SEQ / 128, 24), 256, GSMEM>>>(ah, al, b1h, b1l, nullptr, 0);

    attn_kernel<<<dim3(SEQ / 32, NKV), 256, ATTN_SMEM>>>(mask);

    gemm_mma<<<dim3(SEQ / 128, 16), 256, GSMEM>>>(chh, cll, b2h, b2l, out, 1);
}

// round 17
// speedup vs baseline: 1.5516x; 1.0967x over previous
#include <cuda_runtime.h>
#include <cuda_bf16.h>
#include <math.h>
#include <stdint.h>

#define SEQ   2048
#define HID   1024
#define KDIM  1024
#define NH    16
#define NKV   4
#define DH    64
#define WIN   64

// ---------------------------------------------------------------------------
// Scratch (device globals — no allocation allowed)
// ---------------------------------------------------------------------------
__device__ float g_q[SEQ * HID];
__device__ float g_k[SEQ * NKV * DH];
__device__ float g_v[SEQ * NKV * DH];
__device__ float2 g_sc[SEQ * 32];

__device__ __nv_bfloat16 g_ah[SEQ * KDIM],  g_al[SEQ * KDIM];    // hidden split
__device__ __nv_bfloat16 g_b1h[1536 * KDIM], g_b1l[1536 * KDIM]; // qkv W^T split
__device__ __nv_bfloat16 g_b2h[1024 * KDIM], g_b2l[1024 * KDIM]; // o W^T split
__device__ __nv_bfloat16 g_ch[SEQ * KDIM],  g_cl[SEQ * KDIM];    // attn-out split

// ---------------------------------------------------------------------------
// Baseline-PTX async-copy / ldmatrix / mma helpers (sm_80+, legal in compute_103)
// ---------------------------------------------------------------------------
__device__ __forceinline__ uint32_t smem_u32(const void* p) {
    uint32_t a;
    asm("{ .reg .u64 t; cvta.to.shared.u64 t, %1; cvt.u32.u64 %0, t; }"
        : "=r"(a) : "l"(p));
    return a;
}
__device__ __forceinline__ void cp_async16(uint32_t d, const void* s) {
    asm volatile("cp.async.cg.shared.global [%0], [%1], 16;" :: "r"(d), "l"(s));
}
__device__ __forceinline__ void cp_commit() {
    asm volatile("cp.async.commit_group;" ::: "memory");
}
template <int N> __device__ __forceinline__ void cp_wait() {
    asm volatile("cp.async.wait_group %0;" :: "n"(N) : "memory");
}
__device__ __forceinline__ void ldm_x4(uint32_t* r, uint32_t addr) {
    asm volatile("ldmatrix.sync.aligned.m8n8.x4.shared.b16 {%0,%1,%2,%3}, [%4];"
                 : "=r"(r[0]), "=r"(r[1]), "=r"(r[2]), "=r"(r[3]) : "r"(addr));
}
__device__ __forceinline__ void mma_bf16(float* c, const uint32_t* a,
                                         const uint32_t* b) {
    asm volatile("mma.sync.aligned.m16n8k16.row.col.f32.bf16.bf16.f32 "
                 "{%0,%1,%2,%3}, {%4,%5,%6,%7}, {%8,%9}, {%0,%1,%2,%3};"
                 : "+f"(c[0]), "+f"(c[1]), "+f"(c[2]), "+f"(c[3])
                 : "r"(a[0]), "r"(a[1]), "r"(a[2]), "r"(a[3]),
                   "r"(b[0]), "r"(b[1]));
}

// ---------------------------------------------------------------------------
// Merged conversion kernel (NO fp64 branch — that's what sank the R11 merge):
//   blocks [0, 2048):    hidden fp32 -> bf16 hi/lo split (4 floats/thread)
//   blocks [2048, 4608): weight transpose + split (32x32 tiles)
// ---------------------------------------------------------------------------
__global__ void convert_all(const float* __restrict__ hidden,
                            const float* __restrict__ qw,
                            const float* __restrict__ kw,
                            const float* __restrict__ vw,
                            const float* __restrict__ ow) {
    __shared__ float t[32][33];
    int b = blockIdx.x;
    int tid = threadIdx.x;
    if (b < 2048) {
        int i = b * 256 + tid;                 // < 524288 float4s
        float4 v = ((const float4*)hidden)[i];
        __nv_bfloat16 h0 = __float2bfloat16_rn(v.x);
        __nv_bfloat16 h1 = __float2bfloat16_rn(v.y);
        __nv_bfloat16 h2 = __float2bfloat16_rn(v.z);
        __nv_bfloat16 h3 = __float2bfloat16_rn(v.w);
        __nv_bfloat16 l0 = __float2bfloat16_rn(v.x - __bfloat162float(h0));
        __nv_bfloat16 l1 = __float2bfloat16_rn(v.y - __bfloat162float(h1));
        __nv_bfloat16 l2 = __float2bfloat16_rn(v.z - __bfloat162float(h2));
        __nv_bfloat16 l3 = __float2bfloat16_rn(v.w - __bfloat162float(h3));
        ((__nv_bfloat162*)g_ah)[i * 2]     = __nv_bfloat162(h0, h1);
        ((__nv_bfloat162*)g_ah)[i * 2 + 1] = __nv_bfloat162(h2, h3);
        ((__nv_bfloat162*)g_al)[i * 2]     = __nv_bfloat162(l0, l1);
        ((__nv_bfloat162*)g_al)[i * 2 + 1] = __nv_bfloat162(l2, l3);
    } else {
        int bb = b - 2048;
        const float* w;
        __nv_bfloat16 *th, *tl;
        int Nsrc, roff, local;
        if (bb < 1024)      { w = qw; th = g_b1h; tl = g_b1l; Nsrc = 1024; roff = 0;    local = bb; }
        else if (bb < 1280) { w = kw; th = g_b1h; tl = g_b1l; Nsrc = 256;  roff = 1024; local = bb - 1024; }
        else if (bb < 1536) { w = vw; th = g_b1h; tl = g_b1l; Nsrc = 256;  roff = 1280; local = bb - 1280; }
        else                { w = ow; th = g_b2h; tl = g_b2l; Nsrc = 1024; roff = 0;    local = bb - 1536; }
        int ntn = Nsrc / 32;
        int nb = (local % ntn) * 32;
        int kb = (local / ntn) * 32;
        int tx = tid & 31, ty = tid >> 5;   // (32, 8)
        #pragma unroll
        for (int j = 0; j < 32; j += 8)
            t[ty + j][tx] = w[(size_t)(kb + ty + j) * Nsrc + nb + tx];
        __syncthreads();
        #pragma unroll
        for (int j = 0; j < 32; j += 8) {
            float x = t[tx][ty + j];
            __nv_bfloat16 h = __float2bfloat16_rn(x);
            __nv_bfloat16 l = __float2bfloat16_rn(x - __bfloat162float(h));
            size_t o = (size_t)(roff + nb + ty + j) * KDIM + kb + tx;
            th[o] = h;
            tl[o] = l;
        }
    }
}

// ---------------------------------------------------------------------------
// HMMA GEMM: C = A @ B^T, bf16-split 3-term, fp32 accum.
// CTA tile 128x64, K chunks of 32, cp.async double buffer, 8 warps (4x2),
// each warp 32x32 via 2x4 m16n8k16 tiles. 3 CTAs/SM.  (best-known config)
// mode 0: qkv demux (blockIdx.y -> g_q/g_k/g_v). mode 1: write Cout.
// ---------------------------------------------------------------------------
#define BK      32
#define ROWB    80
#define AMATB   (128 * ROWB)
#define BMATB   (64 * ROWB)
#define STAGEB  (2 * AMATB + 2 * BMATB)   // 30720
#define GSMEM   (2 * STAGEB)              // 61440

__global__ __launch_bounds__(256, 3) void gemm_mma(
    const __nv_bfloat16* __restrict__ Ah, const __nv_bfloat16* __restrict__ Al,
    const __nv_bfloat16* __restrict__ Bh, const __nv_bfloat16* __restrict__ Bl,
    float* __restrict__ Cout, int mode) {
    extern __shared__ char smem[];
    const uint32_t sb = smem_u32(smem);
    const int tid = threadIdx.x;
    const int wid = tid >> 5, lane = tid & 31;
    const int wm = wid >> 1, wn = wid & 1;
    const int m0 = blockIdx.x * 128;
    const int nt = blockIdx.y;
    const int n0 = nt * 64;

    const __nv_bfloat16* gA[2] = { Ah + (size_t)m0 * KDIM, Al + (size_t)m0 * KDIM };
    const __nv_bfloat16* gB[2] = { Bh + (size_t)n0 * KDIM, Bl + (size_t)n0 * KDIM };

    const int arow  = tid >> 1;
    const int ahalf = tid & 1;
    const int brow = tid >> 2;
    const int bseg = tid & 3;

    const int g2    = lane >> 3;
    const int rsub  = ((g2 & 1) << 3) + (lane & 7);
    const int ksubA = (g2 >> 1) * 8;
    const int rsubB = ((g2 >> 1) << 3) + (lane & 7);
    const int ksubB = (g2 & 1) * 8;

    float acc[2][4][4] = {};

    const int NC = KDIM / BK;
    auto load_stage = [&](int c, int buf) {
        uint32_t base = sb + buf * STAGEB;
        const int kc = c * BK;
        #pragma unroll
        for (int m = 0; m < 2; m++) {
            const __nv_bfloat16* src = gA[m] + (size_t)arow * KDIM + kc + ahalf * 16;
            uint32_t dst = base + m * AMATB + arow * ROWB + ahalf * 32;
            cp_async16(dst, src);
            cp_async16(dst + 16, src + 8);
        }
        #pragma unroll
        for (int m = 0; m < 2; m++) {
            const __nv_bfloat16* src = gB[m] + (size_t)brow * KDIM + kc + bseg * 8;
            uint32_t dst = base + 2 * AMATB + m * BMATB + brow * ROWB + bseg * 16;
            cp_async16(dst, src);
        }
        cp_commit();
    };

    load_stage(0, 0);

    for (int c = 0; c < NC; c++) {
        const int buf = c & 1;
        if (c + 1 < NC) {
            load_stage(c + 1, buf ^ 1);
            cp_wait<1>();
        } else {
            cp_wait<0>();
        }
        __syncthreads();

        const uint32_t stage = sb + buf * STAGEB;
        const uint32_t aBase = stage;
        const uint32_t bBase = stage + 2 * AMATB;
        #pragma unroll
        for (int ks = 0; ks < 2; ks++) {
            uint32_t afr[2][4], bhf[2][4], blf[2][4];
            #pragma unroll
            for (int mt = 0; mt < 2; mt++)
                ldm_x4(afr[mt], aBase +
                       (wm * 32 + mt * 16 + rsub) * ROWB + (ks * 16 + ksubA) * 2);
            #pragma unroll
            for (int p = 0; p < 2; p++)
                ldm_x4(bhf[p], bBase +
                       (wn * 32 + p * 16 + rsubB) * ROWB + (ks * 16 + ksubB) * 2);
            #pragma unroll
            for (int mt = 0; mt < 2; mt++)
                #pragma unroll
                for (int n4 = 0; n4 < 4; n4++)
                    mma_bf16(acc[mt][n4], afr[mt], &bhf[n4 >> 1][(n4 & 1) * 2]);
            #pragma unroll
            for (int p = 0; p < 2; p++)
                ldm_x4(blf[p], bBase + BMATB +
                       (wn * 32 + p * 16 + rsubB) * ROWB + (ks * 16 + ksubB) * 2);
            #pragma unroll
            for (int mt = 0; mt < 2; mt++)
                #pragma unroll
                for (int n4 = 0; n4 < 4; n4++)
                    mma_bf16(acc[mt][n4], afr[mt], &blf[n4 >> 1][(n4 & 1) * 2]);
            #pragma unroll
            for (int mt = 0; mt < 2; mt++)
                ldm_x4(afr[mt], aBase + AMATB +
                       (wm * 32 + mt * 16 + rsub) * ROWB + (ks * 16 + ksubA) * 2);
            #pragma unroll
            for (int mt = 0; mt < 2; mt++)
                #pragma unroll
                for (int n4 = 0; n4 < 4; n4++)
                    mma_bf16(acc[mt][n4], afr[mt], &bhf[n4 >> 1][(n4 & 1) * 2]);
        }
        __syncthreads();
    }

    float* C;
    int Nc, nc0;
    if (mode == 0) {
        if (nt < 16)      { C = g_q; Nc = HID;      nc0 = n0; }
        else if (nt < 20) { C = g_k; Nc = NKV * DH; nc0 = (nt - 16) * 64; }
        else              { C = g_v; Nc = NKV * DH; nc0 = (nt - 20) * 64; }
    } else { C = Cout; Nc = HID; nc0 = n0; }
    const int rbase = m0 + wm * 32 + (lane >> 2);
    const int cbase = nc0 + wn * 32 + (lane & 3) * 2;
    #pragma unroll
    for (int mt = 0; mt < 2; mt++)
        #pragma unroll
        for (int n4 = 0; n4 < 4; n4++) {
            int r = rbase + mt * 16;
            int cc = cbase + n4 * 8;
            *(float2*)(C + (size_t)r * Nc + cc) =
                make_float2(acc[mt][n4][0], acc[mt][n4][1]);
            *(float2*)(C + (size_t)(r + 8) * Nc + cc) =
                make_float2(acc[mt][n4][2], acc[mt][n4][3]);
        }
}

// ---------------------------------------------------------------------------
// Sincos table — FP64 pow only for the 32-entry inv_freq table (per block),
// FP64 multiply for the angle (matches reference float64 semantics), then
// accurate float sincosf on the float32 angle (~1e-7 difference).
// ---------------------------------------------------------------------------
__global__ void sincos_table_kernel(const int* __restrict__ pos_ids) {
    __shared__ double invf_s[32];
    int tid = threadIdx.x;
    if (tid < 32)
        invf_s[tid] = pow(10000.0, -(double)tid / 32.0);
    __syncthreads();
    int idx = blockIdx.x * blockDim.x + tid;
    if (idx >= SEQ * 32) return;
    int i = idx & 31;
    int s = idx >> 5;
    int pos = pos_ids[s];
    float ang = (float)((double)pos * invf_s[i]);   // reference rounds to f32
    float sf, cf;
    sincosf(ang, &sf, &cf);
    g_sc[idx] = make_float2(sf, cf);
}

// ---------------------------------------------------------------------------
// Sliding-window attention with fused RoPE (staging) and fused bf16-split
// output (epilogue). Block = (32-query tile, kv head).
// ---------------------------------------------------------------------------
#define ATTN_SMEM ((64 * 97 + 95 * 64 + 128 * 64 + 8 * 4 * 64) * 4)

__global__ __launch_bounds__(256) void attn_kernel(const int* __restrict__ mask) {
    extern __shared__ float smarr[];
    float* kT = smarr;              // [64 d][97]
    float* vS = kT + 64 * 97;       // [95][64]
    float* qs = vS + 95 * 64;       // [128][64]  row r = sl*4 + h
    float* ps = qs + 128 * 64;      // [8 warps][4 h][64]

    const int g  = blockIdx.y;
    const int s0 = blockIdx.x * 32;
    const int tid = threadIdx.x;

    for (int idx = tid; idx < 95 * 32; idx += 256) {
        int j = idx >> 5;
        int d = idx & 31;
        int jg = s0 - 63 + j;
        float r0 = 0.f, r1 = 0.f, v0 = 0.f, v1 = 0.f;
        if (jg >= 0) {
            size_t off = (size_t)jg * (NKV * DH) + g * DH + d;
            float x0 = g_k[off];
            float x1 = g_k[off + 32];
            float2 sc = g_sc[jg * 32 + d];
            r0 = x0 * sc.y - x1 * sc.x;
            r1 = x1 * sc.y + x0 * sc.x;
            v0 = g_v[off];
            v1 = g_v[off + 32];
        }
        kT[d * 97 + j]        = r0;
        kT[(d + 32) * 97 + j] = r1;
        vS[j * 64 + d]        = v0;
        vS[j * 64 + d + 32]   = v1;
    }
    for (int idx = tid; idx < 128 * 32; idx += 256) {
        int r = idx >> 5;
        int d = idx & 31;
        int sl = r >> 2;
        int hl = r & 3;
        int s  = s0 + sl;
        size_t off = (size_t)s * HID + (4 * g + hl) * DH + d;
        float x0 = g_q[off];
        float x1 = g_q[off + 32];
        float2 sc = g_sc[s * 32 + d];
        qs[r * 64 + d]      = x0 * sc.y - x1 * sc.x;
        qs[r * 64 + d + 32] = x1 * sc.y + x0 * sc.x;
    }
    __syncthreads();

    const int warp = tid >> 5;
    const int lane = tid & 31;

    for (int sl_i = 0; sl_i < 4; sl_i++) {
        const int sl = warp * 4 + sl_i;
        const int s  = s0 + sl;
        const int jb = sl;

        float sc0[4] = {}, sc1[4] = {};
        #pragma unroll
        for (int d = 0; d < 64; d++) {
            const float* kr = kT + d * 97 + jb;
            float k0 = kr[lane];
            float k1 = kr[lane + 32];
            #pragma unroll
            for (int h = 0; h < 4; h++) {
                float qd = qs[(sl * 4 + h) * 64 + d];
                sc0[h] += qd * k0;
                sc1[h] += qd * k1;
            }
        }
        const int* mrow = mask + (size_t)s * WIN;
        bool mk0 = mrow[lane] <= 0;
        bool mk1 = mrow[lane + 32] <= 0;

        #pragma unroll
        for (int h = 0; h < 4; h++) {
            float a0 = mk0 ? -1e30f : sc0[h] * 0.125f;
            float a1 = mk1 ? -1e30f : sc1[h] * 0.125f;
            float mx = fmaxf(a0, a1);
            #pragma unroll
            for (int o = 16; o; o >>= 1)
                mx = fmaxf(mx, __shfl_xor_sync(0xffffffffu, mx, o));
            float e0 = __expf(a0 - mx);
            float e1 = __expf(a1 - mx);
            float sum = e0 + e1;
            #pragma unroll
            for (int o = 16; o; o >>= 1)
                sum += __shfl_xor_sync(0xffffffffu, sum, o);
            float inv = 1.f / sum;
            float* pr = ps + (warp * 4 + h) * 64;
            pr[lane]      = e0 * inv;
            pr[lane + 32] = e1 * inv;
        }
        __syncwarp();

        float o0[4] = {}, o1[4] = {};
        const int d0 = lane * 2;
        #pragma unroll
        for (int w = 0; w < 64; w++) {
            float2 vv = *(const float2*)&vS[(jb + w) * 64 + d0];
            #pragma unroll
            for (int h = 0; h < 4; h++) {
                float p = ps[(warp * 4 + h) * 64 + w];
                o0[h] += p * vv.x;
                o1[h] += p * vv.y;
            }
        }
        __syncwarp();

        #pragma unroll
        for (int h = 0; h < 4; h++) {
            size_t off = (size_t)s * HID + (4 * g + h) * DH + d0;
            __nv_bfloat16 h0 = __float2bfloat16_rn(o0[h]);
            __nv_bfloat16 h1 = __float2bfloat16_rn(o1[h]);
            __nv_bfloat16 l0 = __float2bfloat16_rn(o0[h] - __bfloat162float(h0));
            __nv_bfloat16 l1 = __float2bfloat16_rn(o1[h] - __bfloat162float(h1));
            *(__nv_bfloat162*)(g_ch + off) = __nv_bfloat162(h0, h1);
            *(__nv_bfloat162*)(g_cl + off) = __nv_bfloat162(l0, l1);
        }
    }
}

// ---------------------------------------------------------------------------
extern "C" void kernel_launch(void* const* d_in, const int* in_sizes, int n_in,
                              void* d_out, int out_size) {
    const float* hidden = (const float*)d_in[0];
    const int*   mask   = (const int*)d_in[1];
    const int*   pos    = (const int*)d_in[2];
    const float* qw     = (const float*)d_in[3];
    const float* kw     = (const float*)d_in[4];
    const float* vw     = (const float*)d_in[5];
    const float* ow     = (const float*)d_in[6];
    float* out = (float*)d_out;

    __nv_bfloat16 *ah, *al, *b1h, *b1l, *b2h, *b2l, *chh, *cll;
    cudaGetSymbolAddress((void**)&ah,  g_ah);
    cudaGetSymbolAddress((void**)&al,  g_al);
    cudaGetSymbolAddress((void**)&b1h, g_b1h);
    cudaGetSymbolAddress((void**)&b1l, g_b1l);
    cudaGetSymbolAddress((void**)&b2h, g_b2h);
    cudaGetSymbolAddress((void**)&b2l, g_b2l);
    cudaGetSymbolAddress((void**)&chh, g_ch);
    cudaGetSymbolAddress((void**)&cll, g_cl);

    cudaFuncSetAttribute(gemm_mma, cudaFuncAttributeMaxDynamicSharedMemorySize,
                         GSMEM);
    cudaFuncSetAttribute(attn_kernel, cudaFuncAttributeMaxDynamicSharedMemorySize,
                         ATTN_SMEM);

    sincos_table_kernel<<<(SEQ * 32 + 255) / 256, 256>>>(pos);

    convert_all<<<4608, 256>>>(hidden, qw, kw, vw, ow);

    gemm_mma<<<dim3(SEQ / 128, 24), 256, GSMEM>>>(ah, al, b1h, b1l, nullptr, 0);

    attn_kernel<<<dim3(SEQ / 32, NKV), 256, ATTN_SMEM>>>(mask);

    gemm_mma<<<dim3(SEQ / 128, 16), 256, GSMEM>>>(chh, cll, b2h, b2l, out, 1);
}